// round 8
// baseline (speedup 1.0000x reference)
#include <cuda_runtime.h>
#include <math.h>

// ---------------------------------------------------------------------------
// SelectiveModel: B=32768, T=23, H=64, SLOTS=8, VOCAB=64.
//
// Structural collapse: gating MLP -> S[64][64] sigmoid table (recurrence is
// pure integer state); readout L1 -> QP/MP tables; only the 64x64 L2 GEMM
// remains as real FP work.
//
// R7b: 3 kernels. (R7 + alignment fix: sHT stride 68, union sized for it.)
//   P0   : all 12416 independent dot-64s (edot, mdot^T, QP, MP), 1 thr/dot.
//   P1   : S[c][m] combine + sigmoid (4096 entries, 1 thr/entry).
//   main : FUSED recurrence + h gather + 64x64 GEMM per 64-batch block.
//          h tile aliases the dead S-table smem; no global round-trip.
// ---------------------------------------------------------------------------

#define BTOT 32768

__device__ float g_S  [64 * 64];
__device__ float g_QP [66 * 68];
__device__ float g_MP [64 * 68];
__device__ float g_ED [64 * 32];     // edot[c][j]
__device__ float g_MDT[32 * 64];     // mdot transposed [j][m]

// ---------------- packed fp32x2 helpers -------------------------------------
__device__ __forceinline__ unsigned long long pk2(float lo, float hi) {
    unsigned long long r;
    asm("mov.b64 %0, {%1, %2};" : "=l"(r) : "f"(lo), "f"(hi));
    return r;
}
__device__ __forceinline__ void upk2(unsigned long long v, float& lo, float& hi) {
    asm("mov.b64 {%0, %1}, %2;" : "=f"(lo), "=f"(hi) : "l"(v));
}
__device__ __forceinline__ void fma2(unsigned long long& d,
                                     unsigned long long a, unsigned long long b) {
    asm("fma.rn.f32x2 %0, %1, %2, %0;" : "+l"(d) : "l"(a), "l"(b));
}

// ===================== P0: all independent dot products =====================
__global__ void __launch_bounds__(256) p0_kernel(
    const float* __restrict__ embed, const float* __restrict__ gw1,
    const float* __restrict__ rw1,   const float* __restrict__ rb1)
{
    const int idx = blockIdx.x * 256 + threadIdx.x;
    if (idx < 4096) {
        const int r = idx >> 5, j = idx & 31;
        const float* e = embed + (r & 63) * 64;
        const float* w = gw1 + ((r >> 6) * 64) * 32 + j;
        float a0 = 0.f, a1 = 0.f, a2 = 0.f, a3 = 0.f;
        #pragma unroll
        for (int k = 0; k < 64; k += 4) {
            a0 += e[k]     * w[k * 32];
            a1 += e[k + 1] * w[(k + 1) * 32];
            a2 += e[k + 2] * w[(k + 2) * 32];
            a3 += e[k + 3] * w[(k + 3) * 32];
        }
        const float acc = (a0 + a1) + (a2 + a3);
        if (r < 64) g_ED[r * 32 + j] = acc;
        else        g_MDT[j * 64 + (r - 64)] = acc;
    } else if (idx < 8320) {
        const int e2 = idx - 4096;
        const int r = e2 >> 6, j = e2 & 63;
        const float* e = embed + r * 64;
        const float* w = rw1 + j;
        float a0 = rb1[j], a1 = 0.f, a2 = 0.f, a3 = 0.f;
        #pragma unroll
        for (int k = 0; k < 64; k += 4) {
            a0 += e[k]     * w[k * 64];
            a1 += e[k + 1] * w[(k + 1) * 64];
            a2 += e[k + 2] * w[(k + 2) * 64];
            a3 += e[k + 3] * w[(k + 3) * 64];
        }
        g_QP[r * 68 + j] = (a0 + a1) + (a2 + a3);
        if (j < 4) g_QP[r * 68 + 64 + j] = 0.f;
    } else if (idx < 12416) {
        const int e2 = idx - 8320;
        const int r = e2 >> 6, j = e2 & 63;
        const float* e = embed + r * 64;
        const float* w = rw1 + 64 * 64 + j;
        float a0 = 0.f, a1 = 0.f, a2 = 0.f, a3 = 0.f;
        #pragma unroll
        for (int k = 0; k < 64; k += 4) {
            a0 += e[k]     * w[k * 64];
            a1 += e[k + 1] * w[(k + 1) * 64];
            a2 += e[k + 2] * w[(k + 2) * 64];
            a3 += e[k + 3] * w[(k + 3) * 64];
        }
        g_MP[r * 68 + j] = (a0 + a1) + (a2 + a3);
        if (j < 4) g_MP[r * 68 + 64 + j] = 0.f;
    }
}

// ===================== P1: S table combine + sigmoid ========================
__global__ void __launch_bounds__(256) p1_kernel(
    const float* __restrict__ gb1, const float* __restrict__ gw2,
    const float* __restrict__ gb2)
{
    const int idx = blockIdx.x * 256 + threadIdx.x;
    const int c = idx >> 6, m = idx & 63;
    const float* ed = g_ED + c * 32;
    float acc = gb2[0];
    #pragma unroll
    for (int j = 0; j < 32; j++) {
        const float hv = ed[j] + g_MDT[j * 64 + m] + gb1[j];
        acc += fmaxf(hv, 0.f) * gw2[j];
    }
    g_S[c * 64 + m] = 1.f / (1.f + expf(-acc));
}

// ================= main: fused recurrence + h + GEMM ========================
// grid 512 x 256; block = 64 batches.
// smem floats: union(sS [64][65], sHT [64][68]) = 64*68 | sQP[66*68] |
//              sMP[64*68] | sW[64*68] | sRB[64] | sTok (64*24 B)
#define MAIN_SMEM_FLOATS (64 * 68 + 66 * 68 + 64 * 68 + 64 * 68 + 64 + 384)
#define MAIN_SMEM_BYTES  (MAIN_SMEM_FLOATS * 4)

__global__ void __launch_bounds__(256, 3) main_kernel(
    const int* __restrict__ seqs32, const int* __restrict__ qtok32,
    const float* __restrict__ rw2,  const float* __restrict__ rb2,
    float* __restrict__ out)
{
    extern __shared__ float sm[];
    float* sS  = sm;                       // [64][65] (recurrence phase)
    float* sHT = sm;                       // [64 k][68] (GEMM phase, aliases sS)
    float* sQP = sm + 64 * 68;             // [66][68]
    float* sMP = sQP + 66 * 68;            // [64][68]
    float* sW  = sMP + 64 * 68;            // [64 k][68] cols padded
    float* sRB = sW + 64 * 68;             // [64]
    unsigned char* sTok = (unsigned char*)(sRB + 64);
    const int tid = threadIdx.x, bid = blockIdx.x;

    // int64 vs int32 token dtype detection (odd LE words of small int64 == 0)
    const int oddOr = seqs32[1] | seqs32[3] | seqs32[5] | seqs32[7] |
                      seqs32[9] | seqs32[11] | seqs32[13] | seqs32[15];
    const bool is64 = (oddOr == 0);

    // ---- stage tables + weights + tokens ----
    for (int i = tid; i < 4096; i += 256)
        sS[(i >> 6) * 65 + (i & 63)] = g_S[i];
    {
        const float4* g = (const float4*)g_QP; float4* s = (float4*)sQP;
        for (int i = tid; i < 1122; i += 256) s[i] = g[i];
        g = (const float4*)g_MP; s = (float4*)sMP;
        for (int i = tid; i < 1088; i += 256) s[i] = g[i];
        g = (const float4*)rw2;
        for (int i = tid; i < 1024; i += 256)
            ((float4*)sW)[(i >> 4) * 17 + (i & 15)] = g[i];
        if (tid < 16) ((float4*)sRB)[tid] = ((const float4*)rb2)[tid];
    }
    {
        const int base = bid * 64 * 24;
        for (int i = tid; i < 64 * 24; i += 256) {
            const int v = is64 ? seqs32[2 * (base + i)] : seqs32[base + i];
            sTok[i] = (unsigned char)v;
        }
    }
    const int jq = tid & 3;                // j-quarter (adjacent lanes differ)
    const int bl = tid >> 2;               // local batch 0..63
    const int b  = bid * 64 + bl;
    const int qt = is64 ? qtok32[2 * b] : qtok32[b];
    __syncthreads();

    // ---- phase A: recurrence (integer-key argmax; validated R4-R6) ----
    int moff[8];
    {
        const unsigned char* myTok = sTok + bl * 24;
        int mt[8];
        #pragma unroll
        for (int s = 0; s < 8; s++) mt[s] = myTok[s];
        #pragma unroll
        for (int t = 8; t < 23; t++) {
            const int c = myTok[t];
            const float* Srow = sS + c * 65;
            unsigned key[8];
            #pragma unroll
            for (int s = 0; s < 8; s++) {
                const unsigned bits = __float_as_uint(Srow[mt[s]]);
                key[s] = (bits << 2) | (unsigned)(3 - (s & 3));
            }
            const unsigned a0 = max(max(key[0], key[1]), max(key[2], key[3]));
            const unsigned a1 = max(max(key[4], key[5]), max(key[6], key[7]));
            const int bi = ((a1 >> 2) > (a0 >> 2)) ? (4 + 3 - (int)(a1 & 3))
                                                   : (3 - (int)(a0 & 3));
            #pragma unroll
            for (int s = 0; s < 8; s++) if (bi == s) mt[s] = c;
        }
        #pragma unroll
        for (int s = 0; s < 8; s++) moff[s] = mt[s] * 68 + jq * 16;
    }
    __syncthreads();   // all recurrence reads of sS done before sHT overwrite

    // ---- phase B: h gather (16 j's per thread) -> sHT[j][bl] ----
    {
        unsigned long long h[8];
        const float* qp = sQP + qt * 68 + jq * 16;
        #pragma unroll
        for (int i = 0; i < 4; i++) {
            const ulonglong2 q = *(const ulonglong2*)(qp + 4 * i);
            h[2 * i] = q.x; h[2 * i + 1] = q.y;
        }
        const unsigned long long E2 = pk2(0.125f, 0.125f);
        #pragma unroll
        for (int s = 0; s < 8; s++) {
            const float* mp = sMP + moff[s];
            #pragma unroll
            for (int i = 0; i < 4; i++) {
                const ulonglong2 m = *(const ulonglong2*)(mp + 4 * i);
                fma2(h[2 * i],     m.x, E2);
                fma2(h[2 * i + 1], m.y, E2);
            }
        }
        float* ht = sHT + (jq * 16) * 68 + bl;
        #pragma unroll
        for (int i = 0; i < 8; i++) {
            float lo, hi; upk2(h[i], lo, hi);
            ht[(2 * i)     * 68] = fmaxf(lo, 0.f);
            ht[(2 * i + 1) * 68] = fmaxf(hi, 0.f);
        }
    }
    __syncthreads();

    // ---- phase C: GEMM 64b x 64c; warp 8b x 64c; thread 4b x 4c ----
    const int w = tid >> 5, lane = tid & 31;
    const int bg = lane >> 4;              // batch sub-group (0..1)
    const int cg = lane & 15;              // col group (0..15)
    const float* hrow = sHT + w * 8 + bg * 4;     // + k*68 (16B-aligned)
    const float* wcol = sW + cg * 4;              // + k*68

    unsigned long long acc[8];             // 4 batches x 2 col-pairs
    {
        const ulonglong2 r0 = *(const ulonglong2*)(sRB + cg * 4);
        #pragma unroll
        for (int bb = 0; bb < 4; bb++) { acc[bb * 2] = r0.x; acc[bb * 2 + 1] = r0.y; }
    }
    #pragma unroll 8
    for (int k = 0; k < 64; k++) {
        const float4 hv     = *(const float4*)(hrow + k * 68);
        const ulonglong2 wv = *(const ulonglong2*)(wcol + k * 68);
        unsigned long long hb;
        hb = pk2(hv.x, hv.x); fma2(acc[0], hb, wv.x); fma2(acc[1], hb, wv.y);
        hb = pk2(hv.y, hv.y); fma2(acc[2], hb, wv.x); fma2(acc[3], hb, wv.y);
        hb = pk2(hv.z, hv.z); fma2(acc[4], hb, wv.x); fma2(acc[5], hb, wv.y);
        hb = pk2(hv.w, hv.w); fma2(acc[6], hb, wv.x); fma2(acc[7], hb, wv.y);
    }

    const int gb0 = bid * 64 + w * 8 + bg * 4;
    #pragma unroll
    for (int bb = 0; bb < 4; bb++) {
        float4 v;
        upk2(acc[bb * 2],     v.x, v.y);
        upk2(acc[bb * 2 + 1], v.z, v.w);
        *(float4*)(out + (gb0 + bb) * 64 + cg * 4) = v;
    }
}

// ============================== launch ======================================
extern "C" void kernel_launch(void* const* d_in, const int* in_sizes, int n_in,
                              void* d_out, int out_size)
{
    const int*   seqs  = (const int*)  d_in[0];
    const int*   qtok  = (const int*)  d_in[1];
    const float* embed = (const float*)d_in[2];
    const float* gw1   = (const float*)d_in[3];
    const float* gb1   = (const float*)d_in[4];
    const float* gw2   = (const float*)d_in[5];
    const float* gb2   = (const float*)d_in[6];
    const float* rw1   = (const float*)d_in[7];
    const float* rb1   = (const float*)d_in[8];
    const float* rw2   = (const float*)d_in[9];
    const float* rb2   = (const float*)d_in[10];

    cudaFuncSetAttribute(main_kernel,
                         cudaFuncAttributeMaxDynamicSharedMemorySize,
                         MAIN_SMEM_BYTES);

    p0_kernel<<<49, 256>>>(embed, gw1, rw1, rb1);
    p1_kernel<<<16, 256>>>(gb1, gw2, gb2);
    main_kernel<<<512, 256, MAIN_SMEM_BYTES>>>(seqs, qtok, rw2, rb2,
                                               (float*)d_out);
}

// round 9
// speedup vs baseline: 1.1183x; 1.1183x over previous
#include <cuda_runtime.h>
#include <math.h>

// ---------------------------------------------------------------------------
// SelectiveModel: B=32768, T=23, H=64, SLOTS=8, VOCAB=64.
//
// Structural collapse: gating MLP -> S[64][64] sigmoid table (recurrence is
// pure integer state); readout L1 -> QP/MP tables; only the 64x64 L2 GEMM
// remains as real FP work.
//
// R9: R6 4-kernel architecture (best measured split) with latency fixes:
//   p0  : batched 8-deep loads, no reg strangling  (was 8us @ 32 regs)
//   p1  : batched loads, wider grid                (latency chain removed)
//   rh  : unchanged from R6 (validated)
//   gemm: __launch_bounds__(256,4) -> 64-reg k-loop pipelining (was 32 regs)
// ---------------------------------------------------------------------------

#define BTOT 32768

__device__ float g_S  [64 * 64];
__device__ float g_QP [66 * 68];
__device__ float g_MP [64 * 68];
__device__ float g_ED [64 * 32];     // edot[c][j]
__device__ float g_MDT[32 * 64];     // mdot transposed [j][m]
__device__ float g_HT [64 * BTOT];   // k-major h

// ---------------- packed fp32x2 helpers -------------------------------------
__device__ __forceinline__ unsigned long long pk2(float lo, float hi) {
    unsigned long long r;
    asm("mov.b64 %0, {%1, %2};" : "=l"(r) : "f"(lo), "f"(hi));
    return r;
}
__device__ __forceinline__ void upk2(unsigned long long v, float& lo, float& hi) {
    asm("mov.b64 {%0, %1}, %2;" : "=f"(lo), "=f"(hi) : "l"(v));
}
__device__ __forceinline__ void fma2(unsigned long long& d,
                                     unsigned long long a, unsigned long long b) {
    asm("fma.rn.f32x2 %0, %1, %2, %0;" : "+l"(d) : "l"(a), "l"(b));
}

// ===================== P0: all independent dot products =====================
// grid 49 x 256, 1 thread/dot. Loads batched 8-deep (independent LDGs) so
// latency is hidden by MLP, not occupancy. acc[k&3] matches R6 bit-exactly.
__global__ void p0_kernel(
    const float* __restrict__ embed, const float* __restrict__ gw1,
    const float* __restrict__ rw1,   const float* __restrict__ rb1)
{
    const int idx = blockIdx.x * 256 + threadIdx.x;
    if (idx < 4096) {
        const int r = idx >> 5, j = idx & 31;
        const float* e = embed + (r & 63) * 64;
        const float* w = gw1 + ((r >> 6) * 64) * 32 + j;
        float acc[4] = {0.f, 0.f, 0.f, 0.f};
        #pragma unroll
        for (int k0 = 0; k0 < 64; k0 += 8) {
            float wr[8], er[8];
            #pragma unroll
            for (int i = 0; i < 8; i++) { wr[i] = w[(k0 + i) * 32]; er[i] = e[k0 + i]; }
            #pragma unroll
            for (int i = 0; i < 8; i++) acc[i & 3] += er[i] * wr[i];
        }
        const float v = (acc[0] + acc[1]) + (acc[2] + acc[3]);
        if (r < 64) g_ED[r * 32 + j] = v;
        else        g_MDT[j * 64 + (r - 64)] = v;
    } else if (idx < 8320) {
        const int e2 = idx - 4096;
        const int r = e2 >> 6, j = e2 & 63;
        const float* e = embed + r * 64;
        const float* w = rw1 + j;
        float acc[4] = {rb1[j], 0.f, 0.f, 0.f};
        #pragma unroll
        for (int k0 = 0; k0 < 64; k0 += 8) {
            float wr[8], er[8];
            #pragma unroll
            for (int i = 0; i < 8; i++) { wr[i] = w[(k0 + i) * 64]; er[i] = e[k0 + i]; }
            #pragma unroll
            for (int i = 0; i < 8; i++) acc[i & 3] += er[i] * wr[i];
        }
        g_QP[r * 68 + j] = (acc[0] + acc[1]) + (acc[2] + acc[3]);
        if (j < 4) g_QP[r * 68 + 64 + j] = 0.f;
    } else if (idx < 12416) {
        const int e2 = idx - 8320;
        const int r = e2 >> 6, j = e2 & 63;
        const float* e = embed + r * 64;
        const float* w = rw1 + 64 * 64 + j;
        float acc[4] = {0.f, 0.f, 0.f, 0.f};
        #pragma unroll
        for (int k0 = 0; k0 < 64; k0 += 8) {
            float wr[8], er[8];
            #pragma unroll
            for (int i = 0; i < 8; i++) { wr[i] = w[(k0 + i) * 64]; er[i] = e[k0 + i]; }
            #pragma unroll
            for (int i = 0; i < 8; i++) acc[i & 3] += er[i] * wr[i];
        }
        g_MP[r * 68 + j] = (acc[0] + acc[1]) + (acc[2] + acc[3]);
        if (j < 4) g_MP[r * 68 + 64 + j] = 0.f;
    }
}

// ===================== P1: S table combine + sigmoid ========================
// grid 32 x 128; thread = one (c, m). Loads batched 8-deep; single acc chain
// (bit-identical S to R6).
__global__ void p1_kernel(
    const float* __restrict__ gb1, const float* __restrict__ gw2,
    const float* __restrict__ gb2)
{
    const int idx = blockIdx.x * 128 + threadIdx.x;
    const int c = idx >> 6, m = idx & 63;
    const float* ed = g_ED + c * 32;
    float acc = gb2[0];
    #pragma unroll
    for (int j0 = 0; j0 < 32; j0 += 8) {
        float md[8], edv[8], gb[8], gw[8];
        #pragma unroll
        for (int i = 0; i < 8; i++) {
            md[i]  = g_MDT[(j0 + i) * 64 + m];
            edv[i] = ed[j0 + i];
            gb[i]  = gb1[j0 + i];
            gw[i]  = gw2[j0 + i];
        }
        #pragma unroll
        for (int i = 0; i < 8; i++)
            acc += fmaxf(edv[i] + md[i] + gb[i], 0.f) * gw[i];
    }
    g_S[c * 64 + m] = 1.f / (1.f + expf(-acc));
}

// ====================== rh: fused recurrence + h gather =====================
// grid 512 x 256; block = 64 batches. jq = tid&3, bl = tid>>2 (adjacent-lane
// recurrence duplication -> smem broadcast). Unchanged from R6.
#define RH_SMEM_BYTES ((64 * 65 + 66 * 68 + 64 * 68) * 4 + 64 * 24)

__global__ void __launch_bounds__(256, 4) rh_kernel(
    const int* __restrict__ seqs32, const int* __restrict__ qtok32)
{
    extern __shared__ float sm[];
    float* sS  = sm;                       // [64][65]
    float* sQP = sS + 64 * 65;             // [66][68]
    float* sMP = sQP + 66 * 68;            // [64][68]
    unsigned char* sTok = (unsigned char*)(sMP + 64 * 68);
    const int tid = threadIdx.x, bid = blockIdx.x;

    // int64 vs int32 token dtype detection (odd LE words of small int64 == 0)
    const int oddOr = seqs32[1] | seqs32[3] | seqs32[5] | seqs32[7] |
                      seqs32[9] | seqs32[11] | seqs32[13] | seqs32[15];
    const bool is64 = (oddOr == 0);

    for (int i = tid; i < 4096; i += 256)
        sS[(i >> 6) * 65 + (i & 63)] = g_S[i];
    {
        const float4* g = (const float4*)g_QP; float4* s = (float4*)sQP;
        for (int i = tid; i < 1122; i += 256) s[i] = g[i];
        g = (const float4*)g_MP; s = (float4*)sMP;
        for (int i = tid; i < 1088; i += 256) s[i] = g[i];
    }
    {
        const int base = bid * 64 * 24;
        for (int i = tid; i < 64 * 24; i += 256) {
            const int v = is64 ? seqs32[2 * (base + i)] : seqs32[base + i];
            sTok[i] = (unsigned char)v;
        }
    }
    const int jq = tid & 3;                // j-quarter: adjacent lanes differ
    const int bl = tid >> 2;               // local batch 0..63
    const int b  = bid * 64 + bl;
    const int qt = is64 ? qtok32[2 * b] : qtok32[b];
    __syncthreads();

    // ---- recurrence (integer-key argmax; validated R4-R8) ----
    int moff[8];
    {
        const unsigned char* myTok = sTok + bl * 24;
        int mt[8];
        #pragma unroll
        for (int s = 0; s < 8; s++) mt[s] = myTok[s];
        #pragma unroll
        for (int t = 8; t < 23; t++) {
            const int c = myTok[t];
            const float* Srow = sS + c * 65;
            unsigned key[8];
            #pragma unroll
            for (int s = 0; s < 8; s++) {
                const unsigned bits = __float_as_uint(Srow[mt[s]]);
                key[s] = (bits << 2) | (unsigned)(3 - (s & 3));
            }
            const unsigned a0 = max(max(key[0], key[1]), max(key[2], key[3]));
            const unsigned a1 = max(max(key[4], key[5]), max(key[6], key[7]));
            const int bi = ((a1 >> 2) > (a0 >> 2)) ? (4 + 3 - (int)(a1 & 3))
                                                   : (3 - (int)(a0 & 3));
            #pragma unroll
            for (int s = 0; s < 8; s++) if (bi == s) mt[s] = c;
        }
        #pragma unroll
        for (int s = 0; s < 8; s++) moff[s] = mt[s] * 68 + jq * 16;
    }

    // ---- h gather: this thread's 16 j's ----
    unsigned long long h[8];
    {
        const float* qp = sQP + qt * 68 + jq * 16;
        #pragma unroll
        for (int i = 0; i < 4; i++) {
            const ulonglong2 q = *(const ulonglong2*)(qp + 4 * i);
            h[2 * i] = q.x; h[2 * i + 1] = q.y;
        }
    }
    const unsigned long long E2 = pk2(0.125f, 0.125f);
    #pragma unroll
    for (int s = 0; s < 8; s++) {
        const float* mp = sMP + moff[s];
        #pragma unroll
        for (int i = 0; i < 4; i++) {
            const ulonglong2 m = *(const ulonglong2*)(mp + 4 * i);
            fma2(h[2 * i],     m.x, E2);
            fma2(h[2 * i + 1], m.y, E2);
        }
    }
    // relu + k-major store; each (row, 8-consecutive-batch) = full 32B sector
    float* ht = g_HT + (jq * 16) * BTOT + b;
    #pragma unroll
    for (int i = 0; i < 8; i++) {
        float lo, hi; upk2(h[i], lo, hi);
        ht[(2 * i)     * BTOT] = fmaxf(lo, 0.f);
        ht[(2 * i + 1) * BTOT] = fmaxf(hi, 0.f);
    }
}

// ============================ gemm: HT @ rw2 + rb2 ==========================
// grid 512 x 256; block tile 64b x 64c; warp 8b x 64c; thread 4b x 4c.
// (256,4): 64-reg budget so the k-loop LDS batch ahead of the FFMA2 chains.
#define GEMM_SMEM_BYTES ((64 * 68 * 2 + 64) * 4)

__global__ void __launch_bounds__(256, 4) gemm_kernel(
    const float* __restrict__ rw2, const float* __restrict__ rb2,
    float* __restrict__ out)
{
    extern __shared__ float sm[];
    float* sHT = sm;                 // [64 k][68] (64 batches, padded)
    float* sW  = sm + 64 * 68;       // [64 k][68] (64 cols, padded)
    float* sRB = sW + 64 * 68;       // [64]
    const int tid = threadIdx.x, bid = blockIdx.x;
    const int b0 = bid * 64;

    for (int i = tid; i < 1024; i += 256) {
        const int r = i >> 4, c4 = i & 15;
        *(float4*)(sHT + r * 68 + c4 * 4) =
            *(const float4*)(g_HT + r * BTOT + b0 + c4 * 4);
        ((float4*)sW)[r * 17 + c4] = ((const float4*)rw2)[i];
    }
    if (tid < 16) ((float4*)sRB)[tid] = ((const float4*)rb2)[tid];
    __syncthreads();

    const int w = tid >> 5, lane = tid & 31;
    const int bg = lane >> 4;            // batch sub-group (0..1)
    const int cg = lane & 15;            // col group (0..15)
    const float* hrow = sHT + w * 8 + bg * 4;     // + k*68
    const float* wcol = sW + cg * 4;              // + k*68

    unsigned long long acc[8];           // 4 batches x 2 col-pairs
    {
        const ulonglong2 r0 = *(const ulonglong2*)(sRB + cg * 4);
        #pragma unroll
        for (int bb = 0; bb < 4; bb++) { acc[bb * 2] = r0.x; acc[bb * 2 + 1] = r0.y; }
    }
    #pragma unroll 8
    for (int k = 0; k < 64; k++) {
        const float4 hv     = *(const float4*)(hrow + k * 68);
        const ulonglong2 wv = *(const ulonglong2*)(wcol + k * 68);
        unsigned long long hb;
        hb = pk2(hv.x, hv.x); fma2(acc[0], hb, wv.x); fma2(acc[1], hb, wv.y);
        hb = pk2(hv.y, hv.y); fma2(acc[2], hb, wv.x); fma2(acc[3], hb, wv.y);
        hb = pk2(hv.z, hv.z); fma2(acc[4], hb, wv.x); fma2(acc[5], hb, wv.y);
        hb = pk2(hv.w, hv.w); fma2(acc[6], hb, wv.x); fma2(acc[7], hb, wv.y);
    }

    const int gb0 = b0 + w * 8 + bg * 4;
    #pragma unroll
    for (int bb = 0; bb < 4; bb++) {
        float4 v;
        upk2(acc[bb * 2],     v.x, v.y);
        upk2(acc[bb * 2 + 1], v.z, v.w);
        *(float4*)(out + (gb0 + bb) * 64 + cg * 4) = v;
    }
}

// ============================== launch ======================================
extern "C" void kernel_launch(void* const* d_in, const int* in_sizes, int n_in,
                              void* d_out, int out_size)
{
    const int*   seqs  = (const int*)  d_in[0];
    const int*   qtok  = (const int*)  d_in[1];
    const float* embed = (const float*)d_in[2];
    const float* gw1   = (const float*)d_in[3];
    const float* gb1   = (const float*)d_in[4];
    const float* gw2   = (const float*)d_in[5];
    const float* gb2   = (const float*)d_in[6];
    const float* rw1   = (const float*)d_in[7];
    const float* rb1   = (const float*)d_in[8];
    const float* rw2   = (const float*)d_in[9];
    const float* rb2   = (const float*)d_in[10];

    cudaFuncSetAttribute(rh_kernel,
                         cudaFuncAttributeMaxDynamicSharedMemorySize,
                         RH_SMEM_BYTES);
    cudaFuncSetAttribute(gemm_kernel,
                         cudaFuncAttributeMaxDynamicSharedMemorySize,
                         GEMM_SMEM_BYTES);

    p0_kernel<<<49, 256>>>(embed, gw1, rw1, rb1);
    p1_kernel<<<32, 128>>>(gb1, gw2, gb2);
    rh_kernel<<<512, 256, RH_SMEM_BYTES>>>(seqs, qtok);
    gemm_kernel<<<512, 256, GEMM_SMEM_BYTES>>>(rw2, rb2, (float*)d_out);
}